// round 14
// baseline (speedup 1.0000x reference)
#include <cuda_runtime.h>

typedef unsigned long long u64;

#define B_   32
#define ICN  8
#define OCN  8
#define HH   512
#define WW   512
#define MC_  32

// Scratch: per-sample packed filters {w,w} [b][oc][ic][9] and bias [b][oc]
__device__ u64   g_filtp[B_ * OCN * ICN * 9];
__device__ float g_bias [B_ * OCN];

// ---------------- f32x2 helpers (Blackwell packed fp32) ----------------
__device__ __forceinline__ u64 pack2(float lo, float hi) {
    u64 r;
    asm("mov.b64 %0, {%1, %2};" : "=l"(r) : "f"(lo), "f"(hi));
    return r;
}
__device__ __forceinline__ void ffma2(u64 &d, u64 a, u64 b) {
    asm("fma.rn.f32x2 %0, %1, %2, %0;" : "+l"(d) : "l"(a), "l"(b));
}
__device__ __forceinline__ float2 unpack2(u64 v) {
    float2 f;
    asm("mov.b64 {%0, %1}, %2;" : "=f"(f.x), "=f"(f.y) : "l"(v));
    return f;
}

// ---------------- Kernel A: hypernetwork (tiny) ----------------
__global__ void setup_kernel(const float* __restrict__ q,  const float* __restrict__ wm1,
                             const float* __restrict__ bm1, const float* __restrict__ wm2,
                             const float* __restrict__ bm2, const float* __restrict__ wt,
                             const float* __restrict__ bt,  const float* __restrict__ wb,
                             const float* __restrict__ bb) {
    const int b   = blockIdx.x;
    const int tid = threadIdx.x;   // 128 threads

    __shared__ float m1[MC_];
    __shared__ float m2[MC_];

    // Stage 1: m1[c] = leaky( q[b]·wm1[c] + bm1[c] )
    if (tid < MC_) {
        const float* qb = q + b * 64;
        const float* w  = wm1 + tid * 64;
        float s = bm1[tid];
        #pragma unroll
        for (int j = 0; j < 64; j++) s += qb[j] * w[j];
        m1[tid] = s > 0.f ? s : 0.01f * s;
    }
    __syncthreads();

    // Stage 2: m2[c] = leaky( m1 · wm2[c] + bm2[c] )
    if (tid < MC_) {
        const float* w = wm2 + tid * MC_;
        float s = bm2[tid];
        #pragma unroll
        for (int k = 0; k < MC_; k++) s += m1[k] * w[k];
        m2[tid] = s > 0.f ? s : 0.01f * s;
    }
    __syncthreads();

    // Stage 3: filters, written PRE-PACKED as u64 {w,w}
    for (int idx = tid; idx < OCN * ICN * 9; idx += 128) {
        float s = bt[idx / 9];
        #pragma unroll
        for (int c = 0; c < MC_; c++) s += m2[c] * wt[c * (OCN * ICN * 9) + idx];
        g_filtp[b * (OCN * ICN * 9) + idx] = pack2(s, s);
    }

    // Stage 4: bias[b][o]
    if (tid < OCN) {
        float s = bb[tid];
        #pragma unroll
        for (int c = 0; c < MC_; c++) s += m2[c] * wb[tid * MC_ + c];
        g_bias[b * OCN + tid] = s;
    }
}

// ---------------- Kernel B: per-sample 3x3 conv, 4 oc per thread ----------------

// Load 10 values of one input row: columns c0-1 .. c0+8 (c0 multiple of 8).
// Interior via two float4 LDGs; edges via two predicated scalar LDGs (R3 path —
// independent loads, no cross-lane dependency).
__device__ __forceinline__ void load_row(const float* __restrict__ xc, int h, int c0,
                                         float r[10]) {
    if (h >= 0 && h < HH) {
        const float* row = xc + (size_t)h * WW;
        float4 m0 = *(const float4*)(row + c0);
        float4 m1 = *(const float4*)(row + c0 + 4);
        r[0] = (c0 > 0) ? row[c0 - 1] : 0.f;
        r[1] = m0.x; r[2] = m0.y; r[3] = m0.z; r[4] = m0.w;
        r[5] = m1.x; r[6] = m1.y; r[7] = m1.z; r[8] = m1.w;
        r[9] = (c0 + 8 < WW) ? row[c0 + 8] : 0.f;
    } else {
        #pragma unroll
        for (int j = 0; j < 10; j++) r[j] = 0.f;
    }
}

// One dy tap: pack input rows (ra -> lo lane, rb -> hi lane) once, then feed
// 4 output channels x 8 columns x 3 dx taps. Weights are pre-packed u64 in
// SMEM (broadcast LDS.64 — zero ALU pack MOVs for weights).
__device__ __forceinline__ void conv_dy(const u64 (*__restrict__ sfw)[ICN][9], int ic, int dy,
                                        const float ra[10], const float rb[10],
                                        u64 acc[4][8]) {
    u64 p[10];
    #pragma unroll
    for (int j = 0; j < 10; j++) p[j] = pack2(ra[j], rb[j]);

    #pragma unroll
    for (int oc = 0; oc < 4; oc++) {
        const u64 W0 = sfw[oc][ic][dy * 3 + 0];
        const u64 W1 = sfw[oc][ic][dy * 3 + 1];
        const u64 W2 = sfw[oc][ic][dy * 3 + 2];
        #pragma unroll
        for (int j = 0; j < 8; j++) {
            ffma2(acc[oc][j], p[j],     W0);
            ffma2(acc[oc][j], p[j + 1], W1);
            ffma2(acc[oc][j], p[j + 2], W2);
        }
    }
}

__global__ void __launch_bounds__(256, 2)
conv_kernel(const float* __restrict__ x, float* __restrict__ y) {
    const int tid     = threadIdx.x;
    const int colIdx  = tid & 63;       // 64 column-threads, 8 cols each -> 512
    const int rowPair = tid >> 6;       // 4 row-pairs -> 8 rows per block
    const int b       = blockIdx.z;
    const int oc0     = blockIdx.y * 4; // oc quad
    const int h0      = blockIdx.x * 8 + rowPair * 2;  // output rows h0, h0+1
    const int c0      = colIdx * 8;

    __shared__ u64   sfw[4][ICN][9];    // pre-packed {w,w} weights for 4 ocs
    __shared__ float sbias[4];
    for (int i = tid; i < 4 * ICN * 9; i += 256) {
        int ocl = i / (ICN * 9);
        int rem = i - ocl * (ICN * 9);
        sfw[ocl][rem / 9][rem % 9] =
            g_filtp[b * (OCN * ICN * 9) + (oc0 + ocl) * (ICN * 9) + rem];
    }
    if (tid < 4) sbias[tid] = g_bias[b * OCN + oc0 + tid];
    __syncthreads();

    u64 acc[4][8];
    #pragma unroll
    for (int oc = 0; oc < 4; oc++) {
        u64 bz = pack2(sbias[oc], sbias[oc]);
        #pragma unroll
        for (int j = 0; j < 8; j++) acc[oc][j] = bz;
    }

    const float* xb = x + (size_t)b * ICN * HH * WW;

    #pragma unroll 1
    for (int ic = 0; ic < ICN; ic++) {
        const float* xc = xb + (size_t)ic * HH * WW;
        float ra[10], rb[10];
        load_row(xc, h0 - 1, c0, ra);
        load_row(xc, h0,     c0, rb);
        conv_dy(sfw, ic, 0, ra, rb, acc);   // dy=0: rows (h0-1, h0)
        load_row(xc, h0 + 1, c0, ra);
        conv_dy(sfw, ic, 1, rb, ra, acc);   // dy=1: rows (h0,   h0+1)
        load_row(xc, h0 + 2, c0, rb);
        conv_dy(sfw, ic, 2, ra, rb, acc);   // dy=2: rows (h0+1, h0+2)
    }

    // Epilogue: unpack f32x2 lanes (lo = row h0, hi = row h0+1), float4 stores.
    #pragma unroll
    for (int oc = 0; oc < 4; oc++) {
        float lo[8], hi[8];
        #pragma unroll
        for (int j = 0; j < 8; j++) { float2 f = unpack2(acc[oc][j]); lo[j] = f.x; hi[j] = f.y; }
        float* p0 = y + (((size_t)(b * OCN + oc0 + oc)) * HH + h0) * WW + c0;
        *(float4*)(p0)          = make_float4(lo[0], lo[1], lo[2], lo[3]);
        *(float4*)(p0 + 4)      = make_float4(lo[4], lo[5], lo[6], lo[7]);
        *(float4*)(p0 + WW)     = make_float4(hi[0], hi[1], hi[2], hi[3]);
        *(float4*)(p0 + WW + 4) = make_float4(hi[4], hi[5], hi[6], hi[7]);
    }
}

// ---------------- launch ----------------
extern "C" void kernel_launch(void* const* d_in, const int* in_sizes, int n_in,
                              void* d_out, int out_size) {
    const float* q   = (const float*)d_in[0];
    const float* x   = (const float*)d_in[1];
    const float* wm1 = (const float*)d_in[2];
    const float* bm1 = (const float*)d_in[3];
    const float* wm2 = (const float*)d_in[4];
    const float* bm2 = (const float*)d_in[5];
    const float* wt  = (const float*)d_in[6];
    const float* bt  = (const float*)d_in[7];
    const float* wb  = (const float*)d_in[8];
    const float* bb  = (const float*)d_in[9];
    float* y = (float*)d_out;

    setup_kernel<<<B_, 128>>>(q, wm1, bm1, wm2, bm2, wt, bt, wb, bb);

    dim3 grid(HH / 8, OCN / 4, B_);   // 64 x 2 x 32 = 4096 CTAs
    conv_kernel<<<grid, 256>>>(x, y);
}

// round 15
// speedup vs baseline: 1.0012x; 1.0012x over previous
#include <cuda_runtime.h>

typedef unsigned long long u64;

#define B_   32
#define ICN  8
#define OCN  8
#define HH   512
#define WW   512
#define MC_  32

// Scratch: per-sample packed filters {w,w} [b][oc][ic][9] and bias [b][oc]
__device__ u64   g_filtp[B_ * OCN * ICN * 9];
__device__ float g_bias [B_ * OCN];

// ---------------- f32x2 helpers (Blackwell packed fp32) ----------------
__device__ __forceinline__ u64 pack2(float lo, float hi) {
    u64 r;
    asm("mov.b64 %0, {%1, %2};" : "=l"(r) : "f"(lo), "f"(hi));
    return r;
}
__device__ __forceinline__ void ffma2(u64 &d, u64 a, u64 b) {
    asm("fma.rn.f32x2 %0, %1, %2, %0;" : "+l"(d) : "l"(a), "l"(b));
}
__device__ __forceinline__ float2 unpack2(u64 v) {
    float2 f;
    asm("mov.b64 {%0, %1}, %2;" : "=f"(f.x), "=f"(f.y) : "l"(v));
    return f;
}

// ---------------- Kernel A: hypernetwork (tiny) ----------------
__global__ void setup_kernel(const float* __restrict__ q,  const float* __restrict__ wm1,
                             const float* __restrict__ bm1, const float* __restrict__ wm2,
                             const float* __restrict__ bm2, const float* __restrict__ wt,
                             const float* __restrict__ bt,  const float* __restrict__ wb,
                             const float* __restrict__ bb) {
    const int b   = blockIdx.x;
    const int tid = threadIdx.x;   // 128 threads

    __shared__ float m1[MC_];
    __shared__ float m2[MC_];

    // Stage 1: m1[c] = leaky( q[b]·wm1[c] + bm1[c] )
    if (tid < MC_) {
        const float* qb = q + b * 64;
        const float* w  = wm1 + tid * 64;
        float s = bm1[tid];
        #pragma unroll
        for (int j = 0; j < 64; j++) s += qb[j] * w[j];
        m1[tid] = s > 0.f ? s : 0.01f * s;
    }
    __syncthreads();

    // Stage 2: m2[c] = leaky( m1 · wm2[c] + bm2[c] )
    if (tid < MC_) {
        const float* w = wm2 + tid * MC_;
        float s = bm2[tid];
        #pragma unroll
        for (int k = 0; k < MC_; k++) s += m1[k] * w[k];
        m2[tid] = s > 0.f ? s : 0.01f * s;
    }
    __syncthreads();

    // Stage 3: filters, written PRE-PACKED as u64 {w,w}
    for (int idx = tid; idx < OCN * ICN * 9; idx += 128) {
        float s = bt[idx / 9];
        #pragma unroll
        for (int c = 0; c < MC_; c++) s += m2[c] * wt[c * (OCN * ICN * 9) + idx];
        g_filtp[b * (OCN * ICN * 9) + idx] = pack2(s, s);
    }

    // Stage 4: bias[b][o]
    if (tid < OCN) {
        float s = bb[tid];
        #pragma unroll
        for (int c = 0; c < MC_; c++) s += m2[c] * wb[tid * MC_ + c];
        g_bias[b * OCN + tid] = s;
    }
}

// ---------------- Kernel B: per-sample 3x3 conv, 4 oc per thread ----------------

// Load 10 values of one input row: columns c0-1 .. c0+8 (c0 multiple of 8).
// Interior via two float4 LDGs; edges via two predicated scalar LDGs (R3 path —
// independent loads, no cross-lane dependency).
__device__ __forceinline__ void load_row(const float* __restrict__ xc, int h, int c0,
                                         float r[10]) {
    if (h >= 0 && h < HH) {
        const float* row = xc + (size_t)h * WW;
        float4 m0 = *(const float4*)(row + c0);
        float4 m1 = *(const float4*)(row + c0 + 4);
        r[0] = (c0 > 0) ? row[c0 - 1] : 0.f;
        r[1] = m0.x; r[2] = m0.y; r[3] = m0.z; r[4] = m0.w;
        r[5] = m1.x; r[6] = m1.y; r[7] = m1.z; r[8] = m1.w;
        r[9] = (c0 + 8 < WW) ? row[c0 + 8] : 0.f;
    } else {
        #pragma unroll
        for (int j = 0; j < 10; j++) r[j] = 0.f;
    }
}

// One dy tap: pack input rows (ra -> lo lane, rb -> hi lane) once, then feed
// 4 output channels x 8 columns x 3 dx taps. Weights are pre-packed u64 in
// SMEM (broadcast LDS.64 — zero ALU pack MOVs for weights).
__device__ __forceinline__ void conv_dy(const u64 (*__restrict__ sfw)[ICN][9], int ic, int dy,
                                        const float ra[10], const float rb[10],
                                        u64 acc[4][8]) {
    u64 p[10];
    #pragma unroll
    for (int j = 0; j < 10; j++) p[j] = pack2(ra[j], rb[j]);

    #pragma unroll
    for (int oc = 0; oc < 4; oc++) {
        const u64 W0 = sfw[oc][ic][dy * 3 + 0];
        const u64 W1 = sfw[oc][ic][dy * 3 + 1];
        const u64 W2 = sfw[oc][ic][dy * 3 + 2];
        #pragma unroll
        for (int j = 0; j < 8; j++) {
            ffma2(acc[oc][j], p[j],     W0);
            ffma2(acc[oc][j], p[j + 1], W1);
            ffma2(acc[oc][j], p[j + 2], W2);
        }
    }
}

__global__ void __launch_bounds__(256, 2)
conv_kernel(const float* __restrict__ x, float* __restrict__ y) {
    const int tid     = threadIdx.x;
    const int colIdx  = tid & 63;       // 64 column-threads, 8 cols each -> 512
    const int rowPair = tid >> 6;       // 4 row-pairs -> 8 rows per block
    const int b       = blockIdx.z;
    const int oc0     = blockIdx.y * 4; // oc quad
    const int h0      = blockIdx.x * 8 + rowPair * 2;  // output rows h0, h0+1
    const int c0      = colIdx * 8;

    __shared__ u64   sfw[4][ICN][9];    // pre-packed {w,w} weights for 4 ocs
    __shared__ float sbias[4];
    for (int i = tid; i < 4 * ICN * 9; i += 256) {
        int ocl = i / (ICN * 9);
        int rem = i - ocl * (ICN * 9);
        sfw[ocl][rem / 9][rem % 9] =
            g_filtp[b * (OCN * ICN * 9) + (oc0 + ocl) * (ICN * 9) + rem];
    }
    if (tid < 4) sbias[tid] = g_bias[b * OCN + oc0 + tid];
    __syncthreads();

    u64 acc[4][8];
    #pragma unroll
    for (int oc = 0; oc < 4; oc++) {
        u64 bz = pack2(sbias[oc], sbias[oc]);
        #pragma unroll
        for (int j = 0; j < 8; j++) acc[oc][j] = bz;
    }

    const float* xb = x + (size_t)b * ICN * HH * WW;

    #pragma unroll 1
    for (int ic = 0; ic < ICN; ic++) {
        const float* xc = xb + (size_t)ic * HH * WW;
        float ra[10], rb[10];
        load_row(xc, h0 - 1, c0, ra);
        load_row(xc, h0,     c0, rb);
        conv_dy(sfw, ic, 0, ra, rb, acc);   // dy=0: rows (h0-1, h0)
        load_row(xc, h0 + 1, c0, ra);
        conv_dy(sfw, ic, 1, rb, ra, acc);   // dy=1: rows (h0,   h0+1)
        load_row(xc, h0 + 2, c0, rb);
        conv_dy(sfw, ic, 2, ra, rb, acc);   // dy=2: rows (h0+1, h0+2)
    }

    // Epilogue: unpack f32x2 lanes (lo = row h0, hi = row h0+1), float4 stores.
    #pragma unroll
    for (int oc = 0; oc < 4; oc++) {
        float lo[8], hi[8];
        #pragma unroll
        for (int j = 0; j < 8; j++) { float2 f = unpack2(acc[oc][j]); lo[j] = f.x; hi[j] = f.y; }
        float* p0 = y + (((size_t)(b * OCN + oc0 + oc)) * HH + h0) * WW + c0;
        *(float4*)(p0)          = make_float4(lo[0], lo[1], lo[2], lo[3]);
        *(float4*)(p0 + 4)      = make_float4(lo[4], lo[5], lo[6], lo[7]);
        *(float4*)(p0 + WW)     = make_float4(hi[0], hi[1], hi[2], hi[3]);
        *(float4*)(p0 + WW + 4) = make_float4(hi[4], hi[5], hi[6], hi[7]);
    }
}

// ---------------- launch ----------------
extern "C" void kernel_launch(void* const* d_in, const int* in_sizes, int n_in,
                              void* d_out, int out_size) {
    const float* q   = (const float*)d_in[0];
    const float* x   = (const float*)d_in[1];
    const float* wm1 = (const float*)d_in[2];
    const float* bm1 = (const float*)d_in[3];
    const float* wm2 = (const float*)d_in[4];
    const float* bm2 = (const float*)d_in[5];
    const float* wt  = (const float*)d_in[6];
    const float* bt  = (const float*)d_in[7];
    const float* wb  = (const float*)d_in[8];
    const float* bb  = (const float*)d_in[9];
    float* y = (float*)d_out;

    setup_kernel<<<B_, 128>>>(q, wm1, bm1, wm2, bm2, wt, bt, wb, bb);

    dim3 grid(HH / 8, OCN / 4, B_);   // 64 x 2 x 32 = 4096 CTAs
    conv_kernel<<<grid, 256>>>(x, y);
}